// round 14
// baseline (speedup 1.0000x reference)
#include <cuda_runtime.h>
#include <cuda_fp16.h>
#include <cuda_bf16.h>

#define FULL 0xffffffffu
typedef unsigned long long ull;

constexpr int N1 = 50000, E1 = 800000, ET1 = E1 + N1;
constexpr int K1 = 1000,  EG = 8000,  ETG = EG + K1;
constexpr int F  = 128,   H  = 4;
constexpr int NB1 = (N1 + 1023) / 1024;    // 49 blocks (resident-grid safe)

constexpr int SW  = 136;
constexpr int SWC = 132;
constexpr int W_BYTES = 128 * SW * 2;
constexpr int SMEM_TC = 2 * W_BYTES;       // 69632 -> 2 blocks/SM

// ---------------- scratch ----------------------------------------------------
__device__ __align__(16) uint2 g_h1h[N1 * 32];
__device__ __align__(16) float g_as1[N1 * H];
__device__ __align__(16) float g_ad1[N1 * H];
__device__ __align__(16) float g_xout[N1 * F];
__device__ __align__(16) float g_p1[ET1 * H];

__device__ __align__(16) float g_hg[K1 * F];
__device__ __align__(16) float g_asg[K1 * H];
__device__ __align__(16) float g_adg[K1 * H];
__device__ __align__(16) float g_pg[ETG * H];

__device__ int g_deg_all[N1 + 2 * K1];
__device__ int g_rs1[N1];
__device__ int g_bsum[64];
__device__ int g_tick;
__device__ volatile int g_bar1;
__device__ int g_bar2;
__device__ volatile int g_bar3;
__device__ int g_bar4;
__device__ int g_cnt1[N1];
__device__ __align__(16) int2 g_cse1[ET1];
__device__ int g_rsg[K1 + 1];
__device__ int g_cntg[K1];
__device__ __align__(16) int2 g_cseg[ETG];
__device__ int g_gs[K1 + 1];
__device__ int g_cntg2[K1];
__device__ int g_nlist[N1];

// ---------------- helpers ----------------------------------------------------
__device__ __forceinline__ ull pack2(float a, float b) {
    ull r; asm("mov.b64 %0,{%1,%2};" : "=l"(r) : "f"(a), "f"(b)); return r;
}
__device__ __forceinline__ void unpack2(ull v, float& a, float& b) {
    asm("mov.b64 {%0,%1},%2;" : "=f"(a), "=f"(b) : "l"(v));
}
__device__ __forceinline__ ull fma2(ull a, ull b, ull c) {
    ull d; asm("fma.rn.f32x2 %0,%1,%2,%3;" : "=l"(d) : "l"(a), "l"(b), "l"(c)); return d;
}
__device__ __forceinline__ float lrelu(float v) { return v > 0.f ? v : 0.2f * v; }
__device__ __forceinline__ float sel4(float4 v, int i) {
    return i == 0 ? v.x : (i == 1 ? v.y : (i == 2 ? v.z : v.w));
}
__device__ __forceinline__ unsigned saddr(const void* p) {
    return (unsigned)__cvta_generic_to_shared(p);
}
__device__ __forceinline__ void ldsm4(unsigned& r0, unsigned& r1, unsigned& r2, unsigned& r3, unsigned a) {
    asm volatile("ldmatrix.sync.aligned.m8n8.x4.shared.b16 {%0,%1,%2,%3},[%4];"
                 : "=r"(r0), "=r"(r1), "=r"(r2), "=r"(r3) : "r"(a));
}
__device__ __forceinline__ void mma_bf16(float* c, const unsigned* a, const unsigned* b) {
    asm volatile("mma.sync.aligned.m16n8k16.row.col.f32.bf16.bf16.f32 "
                 "{%0,%1,%2,%3},{%4,%5,%6,%7},{%8,%9},{%0,%1,%2,%3};"
                 : "+f"(c[0]), "+f"(c[1]), "+f"(c[2]), "+f"(c[3])
                 : "r"(a[0]), "r"(a[1]), "r"(a[2]), "r"(a[3]), "r"(b[0]), "r"(b[1]));
}
__device__ __forceinline__ void split2(float2 f, unsigned& hi, unsigned& lo) {
    __nv_bfloat162 h2;
    h2.x = __float2bfloat16(f.x);
    h2.y = __float2bfloat16(f.y);
    hi = *(unsigned*)&h2;
    __nv_bfloat162 l2;
    l2.x = __float2bfloat16(f.x - __bfloat162float(h2.x));
    l2.y = __float2bfloat16(f.y - __bfloat162float(h2.y));
    lo = *(unsigned*)&l2;
}
__device__ __forceinline__ int wscan(int v, int lane) {
#pragma unroll
    for (int o = 1; o < 32; o <<= 1) { int t = __shfl_up_sync(FULL, v, o); if (lane >= o) v += t; }
    return v;
}
__device__ __forceinline__ int bscan_incl(int x, int* wsum, int tid) {
    int lane = tid & 31, wid = tid >> 5;
    int v = wscan(x, lane);
    if (lane == 31) wsum[wid] = v;
    __syncthreads();
    if (wid == 0) { int w = wsum[lane]; w = wscan(w, lane); wsum[lane] = w; }
    __syncthreads();
    int r = v + (wid ? wsum[wid - 1] : 0);
    __syncthreads();
    return r;
}
__device__ __forceinline__ float4 h16_to_f4(uint2 u) {
    float2 a = __half22float2(*(__half2*)&u.x), b = __half22float2(*(__half2*)&u.y);
    return make_float4(a.x, a.y, b.x, b.y);
}
template<bool HALF_H>
__device__ __forceinline__ float4 ldh(const void* h, int s, int lane) {
    if (HALF_H) {
        return h16_to_f4(((const uint2*)h)[(size_t)s * 32 + lane]);
    } else {
        return *(const float4*)((const float*)h + (size_t)s * F + 4 * lane);
    }
}

// ---------------- tensor-core GEMM + attention dots (main graph) -------------
__global__ __launch_bounds__(256, 2) void gemm_tc_kernel(
    const float* __restrict__ x, const float* __restrict__ W,
    const float* __restrict__ a_src, const float* __restrict__ a_dst,
    uint2* __restrict__ hout, float* __restrict__ as_, float* __restrict__ ad_, int n)
{
    extern __shared__ char smem[];
    __nv_bfloat16* wh = (__nv_bfloat16*)smem;
    __nv_bfloat16* wl = wh + 128 * SW;
    int tid = threadIdx.x, lane = tid & 31, w = tid >> 5;

    for (int i = tid; i < 128 * 128; i += 256) {
        int k = i >> 7, f = i & 127;
        float v = W[i];
        __nv_bfloat16 hh = __float2bfloat16(v);
        wh[f * SW + k] = hh;
        wl[f * SW + k] = __float2bfloat16(v - __bfloat162float(hh));
    }
    __syncthreads();

    int row0 = blockIdx.x * 128 + w * 16;
    int g = lane >> 2, t = lane & 3;
    const float* xr0 = x + (size_t)min(row0 + g,     n - 1) * F;
    const float* xr8 = x + (size_t)min(row0 + g + 8, n - 1) * F;

    float c[16][4];
#pragma unroll
    for (int nt = 0; nt < 16; nt++) { c[nt][0] = c[nt][1] = c[nt][2] = c[nt][3] = 0.f; }

    int brow  = lane & 7;
    int bkadd = ((lane >> 3) & 1) * 8;
    int bnadd = (lane >> 4) * 8;

#pragma unroll
    for (int ks = 0; ks < 8; ks++) {
        int k0 = ks * 16 + 2 * t;
        float2 f00 = *(const float2*)(xr0 + k0);
        float2 f10 = *(const float2*)(xr8 + k0);
        float2 f01 = *(const float2*)(xr0 + k0 + 8);
        float2 f11 = *(const float2*)(xr8 + k0 + 8);
        unsigned ah[4], al[4];
        split2(f00, ah[0], al[0]);
        split2(f10, ah[1], al[1]);
        split2(f01, ah[2], al[2]);
        split2(f11, ah[3], al[3]);
#pragma unroll
        for (int nt = 0; nt < 16; nt += 2) {
            unsigned bh[4], bl[4];
            unsigned boff = (unsigned)(((nt * 8 + bnadd + brow) * SW + ks * 16 + bkadd) * 2);
            ldsm4(bh[0], bh[1], bh[2], bh[3], saddr(wh) + boff);
            ldsm4(bl[0], bl[1], bl[2], bl[3], saddr(wl) + boff);
            mma_bf16(c[nt],     ah, bh);
            mma_bf16(c[nt],     ah, bl);
            mma_bf16(c[nt],     al, bh);
            mma_bf16(c[nt + 1], ah, bh + 2);
            mma_bf16(c[nt + 1], ah, bl + 2);
            mma_bf16(c[nt + 1], al, bh + 2);
        }
    }
    __syncthreads();

    float* cs = (float*)smem + w * (16 * SWC);
    int crow = lane >> 2;
    int ccol = (lane & 3) * 2;
#pragma unroll
    for (int nt = 0; nt < 16; nt++) {
        *(float2*)&cs[crow * SWC + nt * 8 + ccol]       = make_float2(c[nt][0], c[nt][1]);
        *(float2*)&cs[(crow + 8) * SWC + nt * 8 + ccol] = make_float2(c[nt][2], c[nt][3]);
    }
    __syncwarp();

    float4 asv = *(const float4*)(a_src + 4 * lane);
    float4 adv = *(const float4*)(a_dst + 4 * lane);
    for (int r = 0; r < 16; r++) {
        int grow = row0 + r;
        if (grow >= n) break;
        float4 o = *(const float4*)&cs[r * SWC + 4 * lane];
        __half2 lo = __floats2half2_rn(o.x, o.y);
        __half2 hi = __floats2half2_rn(o.z, o.w);
        uint2 pk; pk.x = *(unsigned*)&lo; pk.y = *(unsigned*)&hi;
        hout[(size_t)grow * 32 + lane] = pk;
        float ds = o.x * asv.x + o.y * asv.y + o.z * asv.z + o.w * asv.w;
        float dd = o.x * adv.x + o.y * adv.y + o.z * adv.z + o.w * adv.w;
#pragma unroll
        for (int off = 4; off; off >>= 1) {
            ds += __shfl_down_sync(FULL, ds, off);
            dd += __shfl_down_sync(FULL, dd, off);
        }
        if ((lane & 7) == 0) {
            as_[grow * H + (lane >> 3)] = ds;
            ad_[grow * H + (lane >> 3)] = dd;
        }
    }
}

// ---------------- FFMA GEMM (group graph, fp32 h out) ------------------------
constexpr int RPW = 8;
__global__ __launch_bounds__(256) void gemm_att_kernel(
    const float* __restrict__ x, const float* __restrict__ W,
    const float* __restrict__ a_src, const float* __restrict__ a_dst,
    float* __restrict__ hout, float* __restrict__ as_, float* __restrict__ ad_, int n)
{
    int lane  = threadIdx.x & 31;
    int warp  = (blockIdx.x * blockDim.x + threadIdx.x) >> 5;
    int nwarp = (gridDim.x * blockDim.x) >> 5;
    for (int r0 = warp * RPW; r0 < n; r0 += nwarp * RPW) {
        float xr[RPW][4];
#pragma unroll
        for (int r = 0; r < RPW; r++) {
            int row = min(r0 + r, n - 1);
            const float* xp = x + (size_t)row * F;
            xr[r][0] = xp[lane];      xr[r][1] = xp[lane + 32];
            xr[r][2] = xp[lane + 64]; xr[r][3] = xp[lane + 96];
        }
        ull acc[RPW][2];
#pragma unroll
        for (int r = 0; r < RPW; r++) { acc[r][0] = 0ull; acc[r][1] = 0ull; }
#pragma unroll
        for (int cc = 0; cc < 4; cc++) {
#pragma unroll 4
            for (int k2 = 0; k2 < 32; k2++) {
                int k = cc * 32 + k2;
                ulonglong2 wv = *(const ulonglong2*)(W + k * F + 4 * lane);
#pragma unroll
                for (int r = 0; r < RPW; r++) {
                    float xk = __shfl_sync(FULL, xr[r][cc], k2);
                    ull xk2 = pack2(xk, xk);
                    acc[r][0] = fma2(xk2, wv.x, acc[r][0]);
                    acc[r][1] = fma2(xk2, wv.y, acc[r][1]);
                }
            }
        }
        float4 asv = *(const float4*)(a_src + 4 * lane);
        float4 adv = *(const float4*)(a_dst + 4 * lane);
#pragma unroll
        for (int r = 0; r < RPW; r++) {
            int row = r0 + r;
            if (row >= n) break;
            float4 o;
            unpack2(acc[r][0], o.x, o.y);
            unpack2(acc[r][1], o.z, o.w);
            *(float4*)(hout + (size_t)row * F + 4 * lane) = o;
            float ds = o.x * asv.x + o.y * asv.y + o.z * asv.z + o.w * asv.w;
            float dd = o.x * adv.x + o.y * adv.y + o.z * adv.z + o.w * adv.w;
#pragma unroll
            for (int off = 4; off; off >>= 1) {
                ds += __shfl_down_sync(FULL, ds, off);
                dd += __shfl_down_sync(FULL, dd, off);
            }
            if ((lane & 7) == 0) {
                as_[row * H + (lane >> 3)] = ds;
                ad_[row * H + (lane >> 3)] = dd;
            }
        }
    }
}

// ---------------- fused hist + scans + scatter (one resident kernel) ---------
__device__ __forceinline__ void grid_barrier(volatile int* barA, int* barB, int tid, int nb)
{
    __syncthreads();
    if (tid == 0) {
        __threadfence();
        atomicAdd((int*)barA, 1);
        while (*barA < nb) __nanosleep(64);
        int t2 = atomicAdd(barB, 1);
        if (t2 == nb - 1) { *barA = 0; *barB = 0; __threadfence(); }
    }
    __syncthreads();
}

__global__ __launch_bounds__(1024) void csr_kernel(
    const int* __restrict__ src1, const int* __restrict__ dst1,
    const int* __restrict__ srcg, const int* __restrict__ dstg,
    const int* __restrict__ gidx)
{
    __shared__ int wsum[32];
    __shared__ int s_last;
    int tid = threadIdx.x, lane = tid & 31;
    int gthreads = gridDim.x * 1024;
    int gt = blockIdx.x * 1024 + tid;
    int* deg1 = g_deg_all;
    int* degg = g_deg_all + N1;
    int* gdeg = g_deg_all + N1 + K1;

    // phase A: histograms
    for (int t = gt; t < ET1; t += gthreads) {
        int d = t < E1 ? dst1[t] : t - E1;
        atomicAdd(&deg1[d], 1);
    }
    for (int t = gt; t < ETG; t += gthreads) {
        int d = t < EG ? dstg[t] : t - EG;
        atomicAdd(&degg[d], 1);
    }
    for (int t = gt; t < N1; t += gthreads)
        atomicAdd(&gdeg[gidx[t]], 1);

    grid_barrier(&g_bar1, &g_bar2, tid, gridDim.x);

    // phase B: tile scans
    int i = gt;
    int x = (i < N1) ? deg1[i] : 0;
    if (i < N1) deg1[i] = 0;
    int incl = bscan_incl(x, wsum, tid);
    if (i < N1) g_rs1[i] = incl - x;
    if (tid == 1023) g_bsum[blockIdx.x] = incl;
    __syncthreads();

    if (tid == 0) {
        __threadfence();
        int t = atomicAdd(&g_tick, 1);
        s_last = (t == (int)gridDim.x - 1) ? 1 : 0;
        if (s_last) atomicExch(&g_tick, 0);
    }
    __syncthreads();
    if (s_last) {
        __threadfence();
        int bv = (tid < NB1) ? g_bsum[tid] : 0;
        int binc = 0;
        if (tid < 64) binc = wscan(bv, lane);
        __syncthreads();
        if (tid == 31) wsum[0] = binc;
        __syncthreads();
        if (tid >= 32 && tid < 64) binc += wsum[0];
        if (tid < NB1) g_bsum[tid] = binc - bv;
        __syncthreads();

        int a1 = (tid < K1) ? degg[tid] : 0;
        if (tid < K1) degg[tid] = 0;
        int inc1 = bscan_incl(a1, wsum, tid);
        if (tid < K1) g_rsg[tid] = inc1 - a1;
        if (tid == 0) g_rsg[K1] = ETG;

        int a2 = (tid < K1) ? gdeg[tid] : 0;
        if (tid < K1) gdeg[tid] = 0;
        int inc2 = bscan_incl(a2, wsum, tid);
        if (tid < K1) g_gs[tid] = inc2 - a2;
        if (tid == 0) g_gs[K1] = N1;
    }

    grid_barrier(&g_bar3, &g_bar4, tid, gridDim.x);

    // phase C: scatters (grid-stride; iterations independent -> pipelined)
    for (int t = gt; t < ET1; t += gthreads) {
        int s = t < E1 ? src1[t] : t - E1;
        int d = t < E1 ? dst1[t] : t - E1;
        int base = g_rs1[d] + g_bsum[d >> 10];
        int pos = base + atomicAdd(&g_cnt1[d], 1);
        g_cse1[pos] = make_int2(s, t);
    }
    for (int t = gt; t < ETG; t += gthreads) {
        int s = t < EG ? srcg[t] : t - EG;
        int d = t < EG ? dstg[t] : t - EG;
        int pos = g_rsg[d] + atomicAdd(&g_cntg[d], 1);
        g_cseg[pos] = make_int2(s, t);
    }
    for (int t = gt; t < N1; t += gthreads) {
        int gi = gidx[t];
        int pos = g_gs[gi] + atomicAdd(&g_cntg2[gi], 1);
        g_nlist[pos] = t;
    }
}

// ---------------- fused softmax + aggregate (512 threads) --------------------
template<bool HALF_H>
__global__ __launch_bounds__(512) void gat_aggr_kernel(
    const int2* __restrict__ cse,
    const int* __restrict__ rs, const int* __restrict__ bsum, int tot,
    int* __restrict__ cnt_reset,
    const float* __restrict__ as_, const float* __restrict__ ad_,
    const void* __restrict__ h, const float* __restrict__ b,
    float* __restrict__ p_csr, float* __restrict__ xout,
    float* __restrict__ alpha_out, int n)
{
    __shared__ float s_al[16 * 32 * 4];
    __shared__ int s_src[16 * 32];
    int lane = threadIdx.x & 31;
    int w = threadIdx.x >> 5;
    int node = (blockIdx.x * blockDim.x + threadIdx.x) >> 5;
    if (node >= n) return;
    int start, end;
    if (bsum) {
        start = rs[node] + bsum[node >> 10];
        end = (node + 1 < n) ? (rs[node + 1] + bsum[(node + 1) >> 10]) : tot;
    } else {
        start = rs[node]; end = rs[node + 1];
    }
    if (lane == 0) cnt_reset[node] = 0;
    int deg = end - start;
    float4 ad4 = *(const float4*)(ad_ + node * 4);
    int hd = lane >> 3;

    if (deg <= 32) {
        int2 se = make_int2(0, 0);
        float4 p = make_float4(0.f, 0.f, 0.f, 0.f);
        float4 z4 = make_float4(0.f, 0.f, 0.f, 0.f);
        if (lane < deg) {
            se = cse[start + lane];
            float4 a4 = *(const float4*)(as_ + se.x * 4);
            p.x = __expf(lrelu(a4.x + ad4.x));
            p.y = __expf(lrelu(a4.y + ad4.y));
            p.z = __expf(lrelu(a4.z + ad4.z));
            p.w = __expf(lrelu(a4.w + ad4.w));
            z4 = p;
        }
#pragma unroll
        for (int o = 16; o; o >>= 1) {
            z4.x += __shfl_xor_sync(FULL, z4.x, o);
            z4.y += __shfl_xor_sync(FULL, z4.y, o);
            z4.z += __shfl_xor_sync(FULL, z4.z, o);
            z4.w += __shfl_xor_sync(FULL, z4.w, o);
        }
        float4 iz = make_float4(1.f / z4.x, 1.f / z4.y, 1.f / z4.z, 1.f / z4.w);
        if (lane < deg) {
            float4 al = make_float4(p.x * iz.x, p.y * iz.y, p.z * iz.z, p.w * iz.w);
            *(float4*)(alpha_out + (size_t)se.y * 4) = al;
            s_src[w * 32 + lane] = se.x;
            *(float4*)&s_al[(w * 32 + lane) * 4] = al;
        }
        __syncwarp();

        const float* alw = s_al + w * 128 + hd;
        const int* srw = s_src + w * 32;
        const uint2* hp = HALF_H ? ((const uint2*)h + lane) : nullptr;
        const float* hf = HALF_H ? nullptr : ((const float*)h + 4 * lane);
        float4 acc = *(const float4*)(b + 4 * lane);
        int e = 0;
        for (; e + 8 <= deg; e += 8) {
            uint2 u[8]; float4 hv[8]; float a[8]; int s[8];
#pragma unroll
            for (int j = 0; j < 8; j++) s[j] = srw[e + j];
#pragma unroll
            for (int j = 0; j < 8; j++) {
                if (HALF_H) u[j] = hp[(size_t)s[j] * 32];
                else        hv[j] = *(const float4*)(hf + (size_t)s[j] * F);
            }
#pragma unroll
            for (int j = 0; j < 8; j++) a[j] = alw[(e + j) * 4];
#pragma unroll
            for (int j = 0; j < 8; j++) {
                if (HALF_H) hv[j] = h16_to_f4(u[j]);
                acc.x = fmaf(a[j], hv[j].x, acc.x);
                acc.y = fmaf(a[j], hv[j].y, acc.y);
                acc.z = fmaf(a[j], hv[j].z, acc.z);
                acc.w = fmaf(a[j], hv[j].w, acc.w);
            }
        }
        for (; e + 4 <= deg; e += 4) {
            uint2 u[4]; float4 hv[4]; float a[4]; int s[4];
#pragma unroll
            for (int j = 0; j < 4; j++) s[j] = srw[e + j];
#pragma unroll
            for (int j = 0; j < 4; j++) {
                if (HALF_H) u[j] = hp[(size_t)s[j] * 32];
                else        hv[j] = *(const float4*)(hf + (size_t)s[j] * F);
            }
#pragma unroll
            for (int j = 0; j < 4; j++) a[j] = alw[(e + j) * 4];
#pragma unroll
            for (int j = 0; j < 4; j++) {
                if (HALF_H) hv[j] = h16_to_f4(u[j]);
                acc.x = fmaf(a[j], hv[j].x, acc.x);
                acc.y = fmaf(a[j], hv[j].y, acc.y);
                acc.z = fmaf(a[j], hv[j].z, acc.z);
                acc.w = fmaf(a[j], hv[j].w, acc.w);
            }
        }
        for (; e < deg; e++) {
            int s = srw[e];
            float al = alw[e * 4];
            float4 hv = ldh<HALF_H>(h, s, lane);
            acc.x = fmaf(al, hv.x, acc.x); acc.y = fmaf(al, hv.y, acc.y);
            acc.z = fmaf(al, hv.z, acc.z); acc.w = fmaf(al, hv.w, acc.w);
        }
        *(float4*)(xout + (size_t)node * F + 4 * lane) = acc;
        return;
    }

    // fallback (deg > 32, rare)
    float4 z4 = make_float4(0.f, 0.f, 0.f, 0.f);
    for (int idx = lane; idx < deg; idx += 32) {
        int2 se2 = cse[start + idx];
        float4 a4 = *(const float4*)(as_ + se2.x * 4);
        float4 p;
        p.x = __expf(lrelu(a4.x + ad4.x));
        p.y = __expf(lrelu(a4.y + ad4.y));
        p.z = __expf(lrelu(a4.z + ad4.z));
        p.w = __expf(lrelu(a4.w + ad4.w));
        *(float4*)(p_csr + (size_t)(start + idx) * 4) = p;
        z4.x += p.x; z4.y += p.y; z4.z += p.z; z4.w += p.w;
    }
#pragma unroll
    for (int o = 16; o; o >>= 1) {
        z4.x += __shfl_xor_sync(FULL, z4.x, o);
        z4.y += __shfl_xor_sync(FULL, z4.y, o);
        z4.z += __shfl_xor_sync(FULL, z4.z, o);
        z4.w += __shfl_xor_sync(FULL, z4.w, o);
    }
    float4 iz = make_float4(1.f / z4.x, 1.f / z4.y, 1.f / z4.z, 1.f / z4.w);
    for (int idx = lane; idx < deg; idx += 32) {
        float4 p = *(const float4*)(p_csr + (size_t)(start + idx) * 4);
        int2 se2 = cse[start + idx];
        float4 al = make_float4(p.x * iz.x, p.y * iz.y, p.z * iz.z, p.w * iz.w);
        *(float4*)(alpha_out + (size_t)se2.y * 4) = al;
    }
    float izh = sel4(iz, hd);
    float4 acc = *(const float4*)(b + 4 * lane);
    for (int e = 0; e < deg; e++) {
        int2 se2 = cse[start + e];
        float4 q = *(const float4*)(p_csr + (size_t)(start + e) * 4);
        float al = sel4(q, hd) * izh;
        float4 hv = ldh<HALF_H>(h, se2.x, lane);
        acc.x = fmaf(al, hv.x, acc.x); acc.y = fmaf(al, hv.y, acc.y);
        acc.z = fmaf(al, hv.z, acc.z); acc.w = fmaf(al, hv.w, acc.w);
    }
    *(float4*)(xout + (size_t)node * F + 4 * lane) = acc;
}

// ---------------- group-attention mixer (f32x2 weighted sum) -----------------
__global__ __launch_bounds__(256) void mix_kernel(
    const float* __restrict__ xout, const float* __restrict__ xg,
    const int* __restrict__ nbr, const int* __restrict__ nlist,
    const int* __restrict__ gstart, float* __restrict__ outf)
{
    __shared__ float srows[17 * 128];
    __shared__ int rowid[17];
    int g = blockIdx.x;
    int tid = threadIdx.x;
    if (tid == 0) g_cntg2[g] = 0;
    if (tid < 17) rowid[tid] = (tid == 0) ? g : nbr[g * 16 + tid - 1];
    __syncthreads();
    for (int i = tid; i < 17 * 128; i += 256)
        srows[i] = xg[(size_t)rowid[i >> 7] * F + (i & 127)];
    __syncthreads();
    int start = gstart[g], end = gstart[g + 1];
    int lane = tid & 31, w = tid >> 5;
    for (int j = start + w; j < end; j += 8) {
        int node = nlist[j];
        float4 x4 = *(const float4*)(xout + (size_t)node * F + 4 * lane);
        float s[17];
#pragma unroll
        for (int k = 0; k < 17; k++) {
            float4 c = *(const float4*)(srows + k * 128 + 4 * lane);
            float dv = x4.x * c.x + x4.y * c.y + x4.z * c.z + x4.w * c.w;
#pragma unroll
            for (int o = 16; o; o >>= 1) dv += __shfl_xor_sync(FULL, dv, o);
            s[k] = dv;
        }
        float mx = s[0];
#pragma unroll
        for (int k = 1; k < 17; k++) mx = fmaxf(mx, s[k]);
        float sum = 0.f;
#pragma unroll
        for (int k = 0; k < 17; k++) { s[k] = __expf(s[k] - mx); sum += s[k]; }
        float inv = 1.f / sum;
        ull g2a = 0ull, g2b = 0ull;
#pragma unroll
        for (int k = 0; k < 17; k++) {
            float wk = s[k] * inv;
            ull wk2 = pack2(wk, wk);
            const ull* c2 = (const ull*)(srows + k * 128 + 4 * lane);
            g2a = fma2(wk2, c2[0], g2a);
            g2b = fma2(wk2, c2[1], g2b);
        }
        float4 g4;
        unpack2(g2a, g4.x, g4.y);
        unpack2(g2b, g4.z, g4.w);
        float4 o4 = make_float4(0.5f * (x4.x + g4.x), 0.5f * (x4.y + g4.y),
                                0.5f * (x4.z + g4.z), 0.5f * (x4.w + g4.w));
        *(float4*)(outf + (size_t)node * F + 4 * lane) = o4;
    }
}

// ---------------- streams/events (static init, pre-checkpoint) --------------
namespace {
struct SideStream {
    cudaStream_t s1 = nullptr;
    cudaEvent_t evFork = nullptr, evCSR = nullptr, evS1 = nullptr;
    bool ok = false;
    SideStream() {
        ok = (cudaStreamCreateWithFlags(&s1, cudaStreamNonBlocking) == cudaSuccess) &&
             (cudaEventCreateWithFlags(&evFork, cudaEventDisableTiming) == cudaSuccess) &&
             (cudaEventCreateWithFlags(&evCSR, cudaEventDisableTiming) == cudaSuccess) &&
             (cudaEventCreateWithFlags(&evS1, cudaEventDisableTiming) == cudaSuccess);
    }
};
SideStream g_ss;
}

// ---------------- host ------------------------------------------------------
extern "C" void kernel_launch(void* const* d_in, const int* in_sizes, int n_in,
                              void* d_out, int out_size)
{
    const float* x    = (const float*)d_in[0];
    const int*   ei   = (const int*)  d_in[1];
    const float* xg   = (const float*)d_in[2];
    const int*   eig  = (const int*)  d_in[3];
    const int*   gidx = (const int*)  d_in[4];
    const int*   nbr  = (const int*)  d_in[5];
    const float* W1   = (const float*)d_in[6];
    const float* as1  = (const float*)d_in[7];
    const float* ad1  = (const float*)d_in[8];
    const float* b1   = (const float*)d_in[9];
    const float* W2   = (const float*)d_in[10];
    const float* as2  = (const float*)d_in[11];
    const float* ad2  = (const float*)d_in[12];
    const float* b2   = (const float*)d_in[13];

    float* out    = (float*)d_out;
    float* out_xf = out;
    float* out_xg = out_xf + (size_t)N1 * F;
    float* out_a1 = out_xg + (size_t)K1 * F;
    float* out_a2 = out_a1 + (size_t)ET1 * H;

    uint2 *p_h1h;
    float *p_as1, *p_ad1, *p_xout, *p_p1;
    float *p_hg, *p_asg, *p_adg, *p_pg;
    int *p_rs1, *p_bsum, *p_cnt1;
    int2 *p_cse1, *p_cseg;
    int *p_rsg, *p_cntg, *p_gs, *p_nlist;
    cudaGetSymbolAddress((void**)&p_h1h,   g_h1h);
    cudaGetSymbolAddress((void**)&p_as1,   g_as1);
    cudaGetSymbolAddress((void**)&p_ad1,   g_ad1);
    cudaGetSymbolAddress((void**)&p_xout,  g_xout);
    cudaGetSymbolAddress((void**)&p_p1,    g_p1);
    cudaGetSymbolAddress((void**)&p_hg,    g_hg);
    cudaGetSymbolAddress((void**)&p_asg,   g_asg);
    cudaGetSymbolAddress((void**)&p_adg,   g_adg);
    cudaGetSymbolAddress((void**)&p_pg,    g_pg);
    cudaGetSymbolAddress((void**)&p_rs1,   g_rs1);
    cudaGetSymbolAddress((void**)&p_bsum,  g_bsum);
    cudaGetSymbolAddress((void**)&p_cnt1,  g_cnt1);
    cudaGetSymbolAddress((void**)&p_cse1,  g_cse1);
    cudaGetSymbolAddress((void**)&p_rsg,   g_rsg);
    cudaGetSymbolAddress((void**)&p_cntg,  g_cntg);
    cudaGetSymbolAddress((void**)&p_cseg,  g_cseg);
    cudaGetSymbolAddress((void**)&p_gs,    g_gs);
    cudaGetSymbolAddress((void**)&p_nlist, g_nlist);

    const int* src1 = ei;
    const int* dst1 = ei + E1;
    const int* srcg = eig;
    const int* dstg = eig + EG;

    bool fork = g_ss.ok;
    cudaStream_t s1 = fork ? g_ss.s1 : (cudaStream_t)0;

    if (fork) {
        cudaEventRecord(g_ss.evFork, 0);
        cudaStreamWaitEvent(s1, g_ss.evFork, 0);
    }

    // ---- side branch A: fused CSR build (#1, one kernel) ----
    csr_kernel<<<NB1, 1024, 0, s1>>>(src1, dst1, srcg, dstg, gidx);
    if (fork) cudaEventRecord(g_ss.evCSR, s1);

    // ---- main branch: tensor-core GEMM (#2) ----
    cudaFuncSetAttribute(gemm_tc_kernel, cudaFuncAttributeMaxDynamicSharedMemorySize, SMEM_TC);
    gemm_tc_kernel<<<(N1 + 127) / 128, 256, SMEM_TC>>>(
        x, W1, as1, ad1, p_h1h, p_as1, p_ad1, N1);

    if (fork) cudaStreamWaitEvent(0, g_ss.evCSR, 0);

    // ---- main softmax + aggregate (#3) ----
    gat_aggr_kernel<true><<<(N1 * 32 + 511) / 512, 512>>>(
        p_cse1, p_rs1, p_bsum, ET1, p_cnt1,
        p_as1, p_ad1, p_h1h, b1, p_p1, p_xout, out_a1, N1);

    // ---- side branch B: group-graph pipeline (#4, #5) ----
    gemm_att_kernel<<<(K1 + RPW * 8 - 1) / (RPW * 8), 256, 0, s1>>>(
        xg, W2, as2, ad2, p_hg, p_asg, p_adg, K1);
    gat_aggr_kernel<false><<<(K1 * 32 + 511) / 512, 512, 0, s1>>>(
        p_cseg, p_rsg, nullptr, ETG, p_cntg,
        p_asg, p_adg, p_hg, b2, p_pg, out_xg, out_a2, K1);
    if (fork) cudaEventRecord(g_ss.evS1, s1);

    if (fork) cudaStreamWaitEvent(0, g_ss.evS1, 0);

    // ---- group-attention mixer (#6) -> x_final ----
    mix_kernel<<<K1, 256>>>(p_xout, out_xg, nbr, p_nlist, p_gs, out_xf);
}

// round 15
// speedup vs baseline: 1.0805x; 1.0805x over previous
#include <cuda_runtime.h>
#include <cuda_fp16.h>
#include <cuda_bf16.h>

#define FULL 0xffffffffu
typedef unsigned long long ull;

constexpr int N1 = 50000, E1 = 800000, ET1 = E1 + N1;
constexpr int K1 = 1000,  EG = 8000,  ETG = EG + K1;
constexpr int F  = 128,   H  = 4;
constexpr int NB1 = (N1 + 1023) / 1024;

constexpr int SW  = 136;
constexpr int SWC = 132;
constexpr int W_BYTES = 128 * SW * 2;
constexpr int SMEM_TC = 2 * W_BYTES;       // 69632 -> 2 blocks/SM

// ---------------- scratch ----------------------------------------------------
__device__ __align__(16) uint2 g_h1h[N1 * 32];
__device__ __align__(16) float g_as1[N1 * H];
__device__ __align__(16) float g_ad1[N1 * H];
__device__ __align__(16) float g_xout[N1 * F];
__device__ __align__(16) float g_p1[ET1 * H];

__device__ __align__(16) float g_hg[K1 * F];
__device__ __align__(16) float g_asg[K1 * H];
__device__ __align__(16) float g_adg[K1 * H];
__device__ __align__(16) float g_pg[ETG * H];

__device__ int g_deg_all[N1 + 2 * K1];
__device__ int g_rs1[N1];
__device__ int g_bsum[64];
__device__ int g_tick;
__device__ volatile int g_bar1;
__device__ int g_bar2;
__device__ int g_cnt1[N1];
__device__ __align__(16) int2 g_cse1[ET1];
__device__ int g_rsg[K1 + 1];
__device__ int g_cntg[K1];
__device__ __align__(16) int2 g_cseg[ETG];
__device__ int g_gs[K1 + 1];
__device__ int g_cntg2[K1];
__device__ int g_nlist[N1];

// ---------------- helpers ----------------------------------------------------
__device__ __forceinline__ ull pack2(float a, float b) {
    ull r; asm("mov.b64 %0,{%1,%2};" : "=l"(r) : "f"(a), "f"(b)); return r;
}
__device__ __forceinline__ void unpack2(ull v, float& a, float& b) {
    asm("mov.b64 {%0,%1},%2;" : "=f"(a), "=f"(b) : "l"(v));
}
__device__ __forceinline__ ull fma2(ull a, ull b, ull c) {
    ull d; asm("fma.rn.f32x2 %0,%1,%2,%3;" : "=l"(d) : "l"(a), "l"(b), "l"(c)); return d;
}
__device__ __forceinline__ float lrelu(float v) { return v > 0.f ? v : 0.2f * v; }
__device__ __forceinline__ float sel4(float4 v, int i) {
    return i == 0 ? v.x : (i == 1 ? v.y : (i == 2 ? v.z : v.w));
}
__device__ __forceinline__ unsigned saddr(const void* p) {
    return (unsigned)__cvta_generic_to_shared(p);
}
__device__ __forceinline__ void ldsm4(unsigned& r0, unsigned& r1, unsigned& r2, unsigned& r3, unsigned a) {
    asm volatile("ldmatrix.sync.aligned.m8n8.x4.shared.b16 {%0,%1,%2,%3},[%4];"
                 : "=r"(r0), "=r"(r1), "=r"(r2), "=r"(r3) : "r"(a));
}
__device__ __forceinline__ void mma_bf16(float* c, const unsigned* a, const unsigned* b) {
    asm volatile("mma.sync.aligned.m16n8k16.row.col.f32.bf16.bf16.f32 "
                 "{%0,%1,%2,%3},{%4,%5,%6,%7},{%8,%9},{%0,%1,%2,%3};"
                 : "+f"(c[0]), "+f"(c[1]), "+f"(c[2]), "+f"(c[3])
                 : "r"(a[0]), "r"(a[1]), "r"(a[2]), "r"(a[3]), "r"(b[0]), "r"(b[1]));
}
__device__ __forceinline__ void split2(float2 f, unsigned& hi, unsigned& lo) {
    __nv_bfloat162 h2;
    h2.x = __float2bfloat16(f.x);
    h2.y = __float2bfloat16(f.y);
    hi = *(unsigned*)&h2;
    __nv_bfloat162 l2;
    l2.x = __float2bfloat16(f.x - __bfloat162float(h2.x));
    l2.y = __float2bfloat16(f.y - __bfloat162float(h2.y));
    lo = *(unsigned*)&l2;
}
__device__ __forceinline__ int wscan(int v, int lane) {
#pragma unroll
    for (int o = 1; o < 32; o <<= 1) { int t = __shfl_up_sync(FULL, v, o); if (lane >= o) v += t; }
    return v;
}
__device__ __forceinline__ int bscan_incl(int x, int* wsum, int tid) {
    int lane = tid & 31, wid = tid >> 5;
    int v = wscan(x, lane);
    if (lane == 31) wsum[wid] = v;
    __syncthreads();
    if (wid == 0) { int w = wsum[lane]; w = wscan(w, lane); wsum[lane] = w; }
    __syncthreads();
    int r = v + (wid ? wsum[wid - 1] : 0);
    __syncthreads();
    return r;
}
__device__ __forceinline__ float4 h16_to_f4(uint2 u) {
    float2 a = __half22float2(*(__half2*)&u.x), b = __half22float2(*(__half2*)&u.y);
    return make_float4(a.x, a.y, b.x, b.y);
}
template<bool HALF_H>
__device__ __forceinline__ float4 ldh(const void* h, int s, int lane) {
    if (HALF_H) {
        return h16_to_f4(((const uint2*)h)[(size_t)s * 32 + lane]);
    } else {
        return *(const float4*)((const float*)h + (size_t)s * F + 4 * lane);
    }
}

// ---------------- tensor-core GEMM + attention dots (both graphs) ------------
template<bool HALF_OUT>
__global__ __launch_bounds__(256, 2) void gemm_tc_kernel(
    const float* __restrict__ x, const float* __restrict__ W,
    const float* __restrict__ a_src, const float* __restrict__ a_dst,
    void* __restrict__ hout, float* __restrict__ as_, float* __restrict__ ad_, int n)
{
    extern __shared__ char smem[];
    __nv_bfloat16* wh = (__nv_bfloat16*)smem;
    __nv_bfloat16* wl = wh + 128 * SW;
    int tid = threadIdx.x, lane = tid & 31, w = tid >> 5;

    for (int i = tid; i < 128 * 128; i += 256) {
        int k = i >> 7, f = i & 127;
        float v = W[i];
        __nv_bfloat16 hh = __float2bfloat16(v);
        wh[f * SW + k] = hh;
        wl[f * SW + k] = __float2bfloat16(v - __bfloat162float(hh));
    }
    __syncthreads();

    int row0 = blockIdx.x * 128 + w * 16;
    int g = lane >> 2, t = lane & 3;
    const float* xr0 = x + (size_t)min(row0 + g,     n - 1) * F;
    const float* xr8 = x + (size_t)min(row0 + g + 8, n - 1) * F;

    float c[16][4];
#pragma unroll
    for (int nt = 0; nt < 16; nt++) { c[nt][0] = c[nt][1] = c[nt][2] = c[nt][3] = 0.f; }

    int brow  = lane & 7;
    int bkadd = ((lane >> 3) & 1) * 8;
    int bnadd = (lane >> 4) * 8;

#pragma unroll
    for (int ks = 0; ks < 8; ks++) {
        int k0 = ks * 16 + 2 * t;
        float2 f00 = *(const float2*)(xr0 + k0);
        float2 f10 = *(const float2*)(xr8 + k0);
        float2 f01 = *(const float2*)(xr0 + k0 + 8);
        float2 f11 = *(const float2*)(xr8 + k0 + 8);
        unsigned ah[4], al[4];
        split2(f00, ah[0], al[0]);
        split2(f10, ah[1], al[1]);
        split2(f01, ah[2], al[2]);
        split2(f11, ah[3], al[3]);
#pragma unroll
        for (int nt = 0; nt < 16; nt += 2) {
            unsigned bh[4], bl[4];
            unsigned boff = (unsigned)(((nt * 8 + bnadd + brow) * SW + ks * 16 + bkadd) * 2);
            ldsm4(bh[0], bh[1], bh[2], bh[3], saddr(wh) + boff);
            ldsm4(bl[0], bl[1], bl[2], bl[3], saddr(wl) + boff);
            mma_bf16(c[nt],     ah, bh);
            mma_bf16(c[nt],     ah, bl);
            mma_bf16(c[nt],     al, bh);
            mma_bf16(c[nt + 1], ah, bh + 2);
            mma_bf16(c[nt + 1], ah, bl + 2);
            mma_bf16(c[nt + 1], al, bh + 2);
        }
    }
    __syncthreads();

    float* cs = (float*)smem + w * (16 * SWC);
    int crow = lane >> 2;
    int ccol = (lane & 3) * 2;
#pragma unroll
    for (int nt = 0; nt < 16; nt++) {
        *(float2*)&cs[crow * SWC + nt * 8 + ccol]       = make_float2(c[nt][0], c[nt][1]);
        *(float2*)&cs[(crow + 8) * SWC + nt * 8 + ccol] = make_float2(c[nt][2], c[nt][3]);
    }
    __syncwarp();

    float4 asv = *(const float4*)(a_src + 4 * lane);
    float4 adv = *(const float4*)(a_dst + 4 * lane);
    for (int r = 0; r < 16; r++) {
        int grow = row0 + r;
        if (grow >= n) break;
        float4 o = *(const float4*)&cs[r * SWC + 4 * lane];
        if (HALF_OUT) {
            __half2 lo = __floats2half2_rn(o.x, o.y);
            __half2 hi = __floats2half2_rn(o.z, o.w);
            uint2 pk; pk.x = *(unsigned*)&lo; pk.y = *(unsigned*)&hi;
            ((uint2*)hout)[(size_t)grow * 32 + lane] = pk;
        } else {
            *(float4*)((float*)hout + (size_t)grow * F + 4 * lane) = o;
        }
        float ds = o.x * asv.x + o.y * asv.y + o.z * asv.z + o.w * asv.w;
        float dd = o.x * adv.x + o.y * adv.y + o.z * adv.z + o.w * adv.w;
#pragma unroll
        for (int off = 4; off; off >>= 1) {
            ds += __shfl_down_sync(FULL, ds, off);
            dd += __shfl_down_sync(FULL, dd, off);
        }
        if ((lane & 7) == 0) {
            as_[grow * H + (lane >> 3)] = ds;
            ad_[grow * H + (lane >> 3)] = dd;
        }
    }
}

// ---------------- fused hist + scans (R13 version) ----------------------------
__global__ __launch_bounds__(1024) void histscan_kernel(
    const int* __restrict__ dst1, const int* __restrict__ dstg,
    const int* __restrict__ gidx)
{
    __shared__ int wsum[32];
    __shared__ int s_last;
    int tid = threadIdx.x, lane = tid & 31;
    int gthreads = gridDim.x * 1024;
    int gt = blockIdx.x * 1024 + tid;
    int* deg1 = g_deg_all;
    int* degg = g_deg_all + N1;
    int* gdeg = g_deg_all + N1 + K1;

    for (int t = gt; t < ET1; t += gthreads) {
        int d = t < E1 ? dst1[t] : t - E1;
        atomicAdd(&deg1[d], 1);
    }
    for (int t = gt; t < ETG; t += gthreads) {
        int d = t < EG ? dstg[t] : t - EG;
        atomicAdd(&degg[d], 1);
    }
    for (int t = gt; t < N1; t += gthreads)
        atomicAdd(&gdeg[gidx[t]], 1);

    __syncthreads();
    if (tid == 0) {
        __threadfence();
        atomicAdd((int*)&g_bar1, 1);
        while (g_bar1 < (int)gridDim.x) __nanosleep(64);
        int t2 = atomicAdd(&g_bar2, 1);
        if (t2 == (int)gridDim.x - 1) { g_bar1 = 0; g_bar2 = 0; __threadfence(); }
    }
    __syncthreads();

    int i = gt;
    int x = (i < N1) ? deg1[i] : 0;
    if (i < N1) deg1[i] = 0;
    int incl = bscan_incl(x, wsum, tid);
    if (i < N1) g_rs1[i] = incl - x;
    if (tid == 1023) g_bsum[blockIdx.x] = incl;
    __syncthreads();

    if (tid == 0) {
        __threadfence();
        int t = atomicAdd(&g_tick, 1);
        s_last = (t == (int)gridDim.x - 1) ? 1 : 0;
        if (s_last) atomicExch(&g_tick, 0);
    }
    __syncthreads();
    if (!s_last) return;
    __threadfence();

    int bv = (tid < NB1) ? g_bsum[tid] : 0;
    int binc = 0;
    if (tid < 64) binc = wscan(bv, lane);
    __syncthreads();
    if (tid == 31) wsum[0] = binc;
    __syncthreads();
    if (tid >= 32 && tid < 64) binc += wsum[0];
    if (tid < NB1) g_bsum[tid] = binc - bv;
    __syncthreads();

    int* degg2 = g_deg_all + N1;
    int a1 = (tid < K1) ? degg2[tid] : 0;
    if (tid < K1) degg2[tid] = 0;
    int inc1 = bscan_incl(a1, wsum, tid);
    if (tid < K1) g_rsg[tid] = inc1 - a1;
    if (tid == 0) g_rsg[K1] = ETG;

    int* gdeg2 = g_deg_all + N1 + K1;
    int a2 = (tid < K1) ? gdeg2[tid] : 0;
    if (tid < K1) gdeg2[tid] = 0;
    int inc2 = bscan_incl(a2, wsum, tid);
    if (tid < K1) g_gs[tid] = inc2 - a2;
    if (tid == 0) g_gs[K1] = N1;
}

__global__ void scatter_all_kernel(const int* __restrict__ src1, const int* __restrict__ dst1,
                                   const int* __restrict__ srcg, const int* __restrict__ dstg,
                                   const int* __restrict__ gidx)
{
    int t = blockIdx.x * blockDim.x + threadIdx.x;
    if (t < ET1) {
        int s = t < E1 ? src1[t] : t - E1;
        int d = t < E1 ? dst1[t] : t - E1;
        int base = g_rs1[d] + g_bsum[d >> 10];
        int pos = base + atomicAdd(&g_cnt1[d], 1);
        g_cse1[pos] = make_int2(s, t);
    }
    if (t < ETG) {
        int s = t < EG ? srcg[t] : t - EG;
        int d = t < EG ? dstg[t] : t - EG;
        int pos = g_rsg[d] + atomicAdd(&g_cntg[d], 1);
        g_cseg[pos] = make_int2(s, t);
    }
    if (t < N1) {
        int gi = gidx[t];
        int pos = g_gs[gi] + atomicAdd(&g_cntg2[gi], 1);
        g_nlist[pos] = t;
    }
}

// ---------------- fused softmax + aggregate (512 threads) --------------------
template<bool HALF_H>
__global__ __launch_bounds__(512) void gat_aggr_kernel(
    const int2* __restrict__ cse,
    const int* __restrict__ rs, const int* __restrict__ bsum, int tot,
    int* __restrict__ cnt_reset,
    const float* __restrict__ as_, const float* __restrict__ ad_,
    const void* __restrict__ h, const float* __restrict__ b,
    float* __restrict__ p_csr, float* __restrict__ xout,
    float* __restrict__ alpha_out, int n)
{
    __shared__ float s_al[16 * 32 * 4];
    __shared__ int s_src[16 * 32];
    int lane = threadIdx.x & 31;
    int w = threadIdx.x >> 5;
    int node = (blockIdx.x * blockDim.x + threadIdx.x) >> 5;
    if (node >= n) return;
    int start, end;
    if (bsum) {
        start = rs[node] + bsum[node >> 10];
        end = (node + 1 < n) ? (rs[node + 1] + bsum[(node + 1) >> 10]) : tot;
    } else {
        start = rs[node]; end = rs[node + 1];
    }
    if (lane == 0) cnt_reset[node] = 0;
    int deg = end - start;
    float4 ad4 = *(const float4*)(ad_ + node * 4);
    int hd = lane >> 3;

    if (deg <= 32) {
        int2 se = make_int2(0, 0);
        float4 p = make_float4(0.f, 0.f, 0.f, 0.f);
        float4 z4 = make_float4(0.f, 0.f, 0.f, 0.f);
        if (lane < deg) {
            se = cse[start + lane];
            float4 a4 = *(const float4*)(as_ + se.x * 4);
            p.x = __expf(lrelu(a4.x + ad4.x));
            p.y = __expf(lrelu(a4.y + ad4.y));
            p.z = __expf(lrelu(a4.z + ad4.z));
            p.w = __expf(lrelu(a4.w + ad4.w));
            z4 = p;
        }
#pragma unroll
        for (int o = 16; o; o >>= 1) {
            z4.x += __shfl_xor_sync(FULL, z4.x, o);
            z4.y += __shfl_xor_sync(FULL, z4.y, o);
            z4.z += __shfl_xor_sync(FULL, z4.z, o);
            z4.w += __shfl_xor_sync(FULL, z4.w, o);
        }
        float4 iz = make_float4(1.f / z4.x, 1.f / z4.y, 1.f / z4.z, 1.f / z4.w);
        if (lane < deg) {
            float4 al = make_float4(p.x * iz.x, p.y * iz.y, p.z * iz.z, p.w * iz.w);
            *(float4*)(alpha_out + (size_t)se.y * 4) = al;
            s_src[w * 32 + lane] = se.x;
            *(float4*)&s_al[(w * 32 + lane) * 4] = al;
        }
        __syncwarp();

        const float* alw = s_al + w * 128 + hd;
        const int* srw = s_src + w * 32;
        const uint2* hp = HALF_H ? ((const uint2*)h + lane) : nullptr;
        const float* hf = HALF_H ? nullptr : ((const float*)h + 4 * lane);
        float4 acc = *(const float4*)(b + 4 * lane);
        int e = 0;
        for (; e + 8 <= deg; e += 8) {
            uint2 u[8]; float4 hv[8]; float a[8]; int s[8];
#pragma unroll
            for (int j = 0; j < 8; j++) s[j] = srw[e + j];
#pragma unroll
            for (int j = 0; j < 8; j++) {
                if (HALF_H) u[j] = hp[(size_t)s[j] * 32];
                else        hv[j] = *(const float4*)(hf + (size_t)s[j] * F);
            }
#pragma unroll
            for (int j = 0; j < 8; j++) a[j] = alw[(e + j) * 4];
#pragma unroll
            for (int j = 0; j < 8; j++) {
                if (HALF_H) hv[j] = h16_to_f4(u[j]);
                acc.x = fmaf(a[j], hv[j].x, acc.x);
                acc.y = fmaf(a[j], hv[j].y, acc.y);
                acc.z = fmaf(a[j], hv[j].z, acc.z);
                acc.w = fmaf(a[j], hv[j].w, acc.w);
            }
        }
        for (; e + 4 <= deg; e += 4) {
            uint2 u[4]; float4 hv[4]; float a[4]; int s[4];
#pragma unroll
            for (int j = 0; j < 4; j++) s[j] = srw[e + j];
#pragma unroll
            for (int j = 0; j < 4; j++) {
                if (HALF_H) u[j] = hp[(size_t)s[j] * 32];
                else        hv[j] = *(const float4*)(hf + (size_t)s[j] * F);
            }
#pragma unroll
            for (int j = 0; j < 4; j++) a[j] = alw[(e + j) * 4];
#pragma unroll
            for (int j = 0; j < 4; j++) {
                if (HALF_H) hv[j] = h16_to_f4(u[j]);
                acc.x = fmaf(a[j], hv[j].x, acc.x);
                acc.y = fmaf(a[j], hv[j].y, acc.y);
                acc.z = fmaf(a[j], hv[j].z, acc.z);
                acc.w = fmaf(a[j], hv[j].w, acc.w);
            }
        }
        for (; e < deg; e++) {
            int s = srw[e];
            float al = alw[e * 4];
            float4 hv = ldh<HALF_H>(h, s, lane);
            acc.x = fmaf(al, hv.x, acc.x); acc.y = fmaf(al, hv.y, acc.y);
            acc.z = fmaf(al, hv.z, acc.z); acc.w = fmaf(al, hv.w, acc.w);
        }
        *(float4*)(xout + (size_t)node * F + 4 * lane) = acc;
        return;
    }

    // fallback (deg > 32, rare)
    float4 z4 = make_float4(0.f, 0.f, 0.f, 0.f);
    for (int idx = lane; idx < deg; idx += 32) {
        int2 se2 = cse[start + idx];
        float4 a4 = *(const float4*)(as_ + se2.x * 4);
        float4 p;
        p.x = __expf(lrelu(a4.x + ad4.x));
        p.y = __expf(lrelu(a4.y + ad4.y));
        p.z = __expf(lrelu(a4.z + ad4.z));
        p.w = __expf(lrelu(a4.w + ad4.w));
        *(float4*)(p_csr + (size_t)(start + idx) * 4) = p;
        z4.x += p.x; z4.y += p.y; z4.z += p.z; z4.w += p.w;
    }
#pragma unroll
    for (int o = 16; o; o >>= 1) {
        z4.x += __shfl_xor_sync(FULL, z4.x, o);
        z4.y += __shfl_xor_sync(FULL, z4.y, o);
        z4.z += __shfl_xor_sync(FULL, z4.z, o);
        z4.w += __shfl_xor_sync(FULL, z4.w, o);
    }
    float4 iz = make_float4(1.f / z4.x, 1.f / z4.y, 1.f / z4.z, 1.f / z4.w);
    for (int idx = lane; idx < deg; idx += 32) {
        float4 p = *(const float4*)(p_csr + (size_t)(start + idx) * 4);
        int2 se2 = cse[start + idx];
        float4 al = make_float4(p.x * iz.x, p.y * iz.y, p.z * iz.z, p.w * iz.w);
        *(float4*)(alpha_out + (size_t)se2.y * 4) = al;
    }
    float izh = sel4(iz, hd);
    float4 acc = *(const float4*)(b + 4 * lane);
    for (int e = 0; e < deg; e++) {
        int2 se2 = cse[start + e];
        float4 q = *(const float4*)(p_csr + (size_t)(start + e) * 4);
        float al = sel4(q, hd) * izh;
        float4 hv = ldh<HALF_H>(h, se2.x, lane);
        acc.x = fmaf(al, hv.x, acc.x); acc.y = fmaf(al, hv.y, acc.y);
        acc.z = fmaf(al, hv.z, acc.z); acc.w = fmaf(al, hv.w, acc.w);
    }
    *(float4*)(xout + (size_t)node * F + 4 * lane) = acc;
}

// ---------------- group-attention mixer (f32x2 weighted sum) -----------------
__global__ __launch_bounds__(256) void mix_kernel(
    const float* __restrict__ xout, const float* __restrict__ xg,
    const int* __restrict__ nbr, const int* __restrict__ nlist,
    const int* __restrict__ gstart, float* __restrict__ outf)
{
    __shared__ float srows[17 * 128];
    __shared__ int rowid[17];
    int g = blockIdx.x;
    int tid = threadIdx.x;
    if (tid == 0) g_cntg2[g] = 0;
    if (tid < 17) rowid[tid] = (tid == 0) ? g : nbr[g * 16 + tid - 1];
    __syncthreads();
    for (int i = tid; i < 17 * 128; i += 256)
        srows[i] = xg[(size_t)rowid[i >> 7] * F + (i & 127)];
    __syncthreads();
    int start = gstart[g], end = gstart[g + 1];
    int lane = tid & 31, w = tid >> 5;
    for (int j = start + w; j < end; j += 8) {
        int node = nlist[j];
        float4 x4 = *(const float4*)(xout + (size_t)node * F + 4 * lane);
        float s[17];
#pragma unroll
        for (int k = 0; k < 17; k++) {
            float4 c = *(const float4*)(srows + k * 128 + 4 * lane);
            float dv = x4.x * c.x + x4.y * c.y + x4.z * c.z + x4.w * c.w;
#pragma unroll
            for (int o = 16; o; o >>= 1) dv += __shfl_xor_sync(FULL, dv, o);
            s[k] = dv;
        }
        float mx = s[0];
#pragma unroll
        for (int k = 1; k < 17; k++) mx = fmaxf(mx, s[k]);
        float sum = 0.f;
#pragma unroll
        for (int k = 0; k < 17; k++) { s[k] = __expf(s[k] - mx); sum += s[k]; }
        float inv = 1.f / sum;
        ull g2a = 0ull, g2b = 0ull;
#pragma unroll
        for (int k = 0; k < 17; k++) {
            float wk = s[k] * inv;
            ull wk2 = pack2(wk, wk);
            const ull* c2 = (const ull*)(srows + k * 128 + 4 * lane);
            g2a = fma2(wk2, c2[0], g2a);
            g2b = fma2(wk2, c2[1], g2b);
        }
        float4 g4;
        unpack2(g2a, g4.x, g4.y);
        unpack2(g2b, g4.z, g4.w);
        float4 o4 = make_float4(0.5f * (x4.x + g4.x), 0.5f * (x4.y + g4.y),
                                0.5f * (x4.z + g4.z), 0.5f * (x4.w + g4.w));
        *(float4*)(outf + (size_t)node * F + 4 * lane) = o4;
    }
}

// ---------------- streams/events (static init, pre-checkpoint) --------------
namespace {
struct SideStream {
    cudaStream_t s1 = nullptr;
    cudaEvent_t evFork = nullptr, evCSR = nullptr, evS1 = nullptr;
    bool ok = false;
    SideStream() {
        ok = (cudaStreamCreateWithFlags(&s1, cudaStreamNonBlocking) == cudaSuccess) &&
             (cudaEventCreateWithFlags(&evFork, cudaEventDisableTiming) == cudaSuccess) &&
             (cudaEventCreateWithFlags(&evCSR, cudaEventDisableTiming) == cudaSuccess) &&
             (cudaEventCreateWithFlags(&evS1, cudaEventDisableTiming) == cudaSuccess);
    }
};
SideStream g_ss;
}

// ---------------- host ------------------------------------------------------
extern "C" void kernel_launch(void* const* d_in, const int* in_sizes, int n_in,
                              void* d_out, int out_size)
{
    const float* x    = (const float*)d_in[0];
    const int*   ei   = (const int*)  d_in[1];
    const float* xg   = (const float*)d_in[2];
    const int*   eig  = (const int*)  d_in[3];
    const int*   gidx = (const int*)  d_in[4];
    const int*   nbr  = (const int*)  d_in[5];
    const float* W1   = (const float*)d_in[6];
    const float* as1  = (const float*)d_in[7];
    const float* ad1  = (const float*)d_in[8];
    const float* b1   = (const float*)d_in[9];
    const float* W2   = (const float*)d_in[10];
    const float* as2  = (const float*)d_in[11];
    const float* ad2  = (const float*)d_in[12];
    const float* b2   = (const float*)d_in[13];

    float* out    = (float*)d_out;
    float* out_xf = out;
    float* out_xg = out_xf + (size_t)N1 * F;
    float* out_a1 = out_xg + (size_t)K1 * F;
    float* out_a2 = out_a1 + (size_t)ET1 * H;

    uint2 *p_h1h;
    float *p_as1, *p_ad1, *p_xout, *p_p1;
    float *p_hg, *p_asg, *p_adg, *p_pg;
    int *p_rs1, *p_bsum, *p_cnt1;
    int2 *p_cse1, *p_cseg;
    int *p_rsg, *p_cntg, *p_gs, *p_nlist;
    cudaGetSymbolAddress((void**)&p_h1h,   g_h1h);
    cudaGetSymbolAddress((void**)&p_as1,   g_as1);
    cudaGetSymbolAddress((void**)&p_ad1,   g_ad1);
    cudaGetSymbolAddress((void**)&p_xout,  g_xout);
    cudaGetSymbolAddress((void**)&p_p1,    g_p1);
    cudaGetSymbolAddress((void**)&p_hg,    g_hg);
    cudaGetSymbolAddress((void**)&p_asg,   g_asg);
    cudaGetSymbolAddress((void**)&p_adg,   g_adg);
    cudaGetSymbolAddress((void**)&p_pg,    g_pg);
    cudaGetSymbolAddress((void**)&p_rs1,   g_rs1);
    cudaGetSymbolAddress((void**)&p_bsum,  g_bsum);
    cudaGetSymbolAddress((void**)&p_cnt1,  g_cnt1);
    cudaGetSymbolAddress((void**)&p_cse1,  g_cse1);
    cudaGetSymbolAddress((void**)&p_rsg,   g_rsg);
    cudaGetSymbolAddress((void**)&p_cntg,  g_cntg);
    cudaGetSymbolAddress((void**)&p_cseg,  g_cseg);
    cudaGetSymbolAddress((void**)&p_gs,    g_gs);
    cudaGetSymbolAddress((void**)&p_nlist, g_nlist);

    const int* src1 = ei;
    const int* dst1 = ei + E1;
    const int* srcg = eig;
    const int* dstg = eig + EG;

    bool fork = g_ss.ok;
    cudaStream_t s1 = fork ? g_ss.s1 : (cudaStream_t)0;

    if (fork) {
        cudaEventRecord(g_ss.evFork, 0);
        cudaStreamWaitEvent(s1, g_ss.evFork, 0);
    }

    cudaFuncSetAttribute(gemm_tc_kernel<true>,  cudaFuncAttributeMaxDynamicSharedMemorySize, SMEM_TC);
    cudaFuncSetAttribute(gemm_tc_kernel<false>, cudaFuncAttributeMaxDynamicSharedMemorySize, SMEM_TC);

    // ---- side branch A: CSR build (#1, #2) ----
    histscan_kernel<<<NB1, 1024, 0, s1>>>(dst1, dstg, gidx);
    scatter_all_kernel<<<(ET1 + 255) / 256, 256, 0, s1>>>(src1, dst1, srcg, dstg, gidx);
    if (fork) cudaEventRecord(g_ss.evCSR, s1);

    // ---- main branch: tensor-core GEMM (#3) ----
    gemm_tc_kernel<true><<<(N1 + 127) / 128, 256, SMEM_TC>>>(
        x, W1, as1, ad1, p_h1h, p_as1, p_ad1, N1);

    if (fork) cudaStreamWaitEvent(0, g_ss.evCSR, 0);

    // ---- main softmax + aggregate (#4) ----
    gat_aggr_kernel<true><<<(N1 * 32 + 511) / 512, 512>>>(
        p_cse1, p_rs1, p_bsum, ET1, p_cnt1,
        p_as1, p_ad1, p_h1h, b1, p_p1, p_xout, out_a1, N1);

    // ---- side branch B: group-graph pipeline (#5 TC gemm, #6 aggr) ----
    gemm_tc_kernel<false><<<(K1 + 127) / 128, 256, SMEM_TC, s1>>>(
        xg, W2, as2, ad2, p_hg, p_asg, p_adg, K1);
    gat_aggr_kernel<false><<<(K1 * 32 + 511) / 512, 512, 0, s1>>>(
        p_cseg, p_rsg, nullptr, ETG, p_cntg,
        p_asg, p_adg, p_hg, b2, p_pg, out_xg, out_a2, K1);
    if (fork) cudaEventRecord(g_ss.evS1, s1);

    if (fork) cudaStreamWaitEvent(0, g_ss.evS1, 0);

    // ---- group-attention mixer (#7) -> x_final ----
    mix_kernel<<<K1, 256>>>(p_xout, out_xg, nbr, p_nlist, p_gs, out_xf);
}